// round 1
// baseline (speedup 1.0000x reference)
#include <cuda_runtime.h>
#include <cuda_bf16.h>
#include <math.h>

// Problem constants
#define BATCH 4096
#define DIN   1024
#define DH    2048
#define DOUT  1024
#define NEXP  16

// GEMM tiling
#define BM 128
#define BN 128
#define BK 16
#define SPAD 132   // padded leading dim (floats) for smem tiles; 16B-aligned rows

// Scratch (device globals — no allocation allowed)
__device__ float g_x1[BATCH * DH];   // tanh(obs @ pre_w^T + pre_b)
__device__ float g_x2[BATCH * DH];   // tanh(expert output)
__device__ int   g_rows[BATCH];      // row indices grouped by expert
__device__ int   g_cnt[NEXP];
__device__ int   g_off[NEXP];

// ---------------------------------------------------------------------------
// Group rows by expert index (single block; deterministic output values —
// intra-group order is irrelevant since each row's result is independent).
// ---------------------------------------------------------------------------
__global__ void group_kernel(const int* __restrict__ idx)
{
    __shared__ int s_cnt[NEXP];
    __shared__ int s_off[NEXP];
    __shared__ int s_fill[NEXP];
    int t = threadIdx.x;
    if (t < NEXP) s_cnt[t] = 0;
    __syncthreads();
    for (int b = t; b < BATCH; b += blockDim.x)
        atomicAdd(&s_cnt[idx[b]], 1);
    __syncthreads();
    if (t == 0) {
        int acc = 0;
        for (int e = 0; e < NEXP; e++) {
            s_off[e]  = acc;
            acc      += s_cnt[e];
            s_fill[e] = 0;
        }
    }
    __syncthreads();
    for (int b = t; b < BATCH; b += blockDim.x) {
        int e = idx[b];
        int p = s_off[e] + atomicAdd(&s_fill[e], 1);
        g_rows[p] = b;
    }
    if (t < NEXP) { g_cnt[t] = s_cnt[t]; g_off[t] = s_off[t]; }
}

// ---------------------------------------------------------------------------
// Fused GEMM body: C[m, :] = tanh(A[m, :] @ B^T + bias), optional row gather.
// A: [?, K] row-major (rows selected via rowmap if non-null)
// B: [N, K] row-major  (i.e. we compute A·B^T)
// C: [?, N] row-major  (row = rowmap[m] if gather, else m)
// Block tile BMxBN, K-step BK. 256 threads, 8x8 per-thread micro-tile.
// ---------------------------------------------------------------------------
__device__ __forceinline__ void gemm_tanh_body(
    const float* __restrict__ A, const float* __restrict__ B,
    const float* __restrict__ bias, float* __restrict__ C,
    int M, int N, int K, const int* __restrict__ rowmap,
    int mblk, int nblk)
{
    __shared__ float As[BK][SPAD];
    __shared__ float Bs[BK][SPAD];

    const int t  = threadIdx.x;
    const int m0 = mblk * BM;
    const int n0 = nblk * BN;

    // Per-thread global-load coordinates (2 float4 loads each for A and B).
    // lin in [0,512): row = lin/4 (coalesced), c4 = lin%4 (16-float K slice).
    int   rowL[2], c4L[2];
    const float* aptr[2];
    const float* bptr[2];
    bool  avld[2];
#pragma unroll
    for (int l = 0; l < 2; l++) {
        int lin = t + l * 256;
        int row = lin >> 2;
        int c4  = lin & 3;
        rowL[l] = row;
        c4L[l]  = c4;
        int gm = m0 + row;
        int ar;
        if (rowmap) { ar = (gm < M) ? rowmap[gm] : 0; }
        else        { ar = (gm < M) ? gm : 0; }
        avld[l] = (gm < M);
        aptr[l] = A + (size_t)ar * K + c4 * 4;
        bptr[l] = B + (size_t)(n0 + row) * K + c4 * 4;
    }

    const int tm = t >> 4;     // 0..15
    const int tn = t & 15;     // 0..15

    float acc[8][8];
#pragma unroll
    for (int i = 0; i < 8; i++)
#pragma unroll
        for (int j = 0; j < 8; j++) acc[i][j] = 0.0f;

    // Prologue: fetch tile 0 into registers
    float4 ra[2], rb[2];
#pragma unroll
    for (int l = 0; l < 2; l++) {
        ra[l] = avld[l] ? *(const float4*)(aptr[l]) : make_float4(0.f, 0.f, 0.f, 0.f);
        rb[l] = *(const float4*)(bptr[l]);
    }

    const int KT = K / BK;
    for (int kt = 0; kt < KT; kt++) {
        // stage registers -> smem (transposed: [k][row])
#pragma unroll
        for (int l = 0; l < 2; l++) {
            int k = c4L[l] * 4;
            int r = rowL[l];
            As[k + 0][r] = ra[l].x;
            As[k + 1][r] = ra[l].y;
            As[k + 2][r] = ra[l].z;
            As[k + 3][r] = ra[l].w;
            Bs[k + 0][r] = rb[l].x;
            Bs[k + 1][r] = rb[l].y;
            Bs[k + 2][r] = rb[l].z;
            Bs[k + 3][r] = rb[l].w;
        }
        __syncthreads();

        // prefetch next tile while computing this one
        if (kt + 1 < KT) {
            int koff = (kt + 1) * BK;
#pragma unroll
            for (int l = 0; l < 2; l++) {
                ra[l] = avld[l] ? *(const float4*)(aptr[l] + koff)
                                : make_float4(0.f, 0.f, 0.f, 0.f);
                rb[l] = *(const float4*)(bptr[l] + koff);
            }
        }

#pragma unroll
        for (int k = 0; k < BK; k++) {
            float af[8], bf[8];
            *(float4*)&af[0] = *(const float4*)&As[k][tm * 8 + 0];
            *(float4*)&af[4] = *(const float4*)&As[k][tm * 8 + 4];
            *(float4*)&bf[0] = *(const float4*)&Bs[k][tn * 8 + 0];
            *(float4*)&bf[4] = *(const float4*)&Bs[k][tn * 8 + 4];
#pragma unroll
            for (int i = 0; i < 8; i++)
#pragma unroll
                for (int j = 0; j < 8; j++)
                    acc[i][j] = fmaf(af[i], bf[j], acc[i][j]);
        }
        __syncthreads();
    }

    // Epilogue: bias + tanh + (scattered) store
    float bv[8];
#pragma unroll
    for (int j = 0; j < 8; j++) bv[j] = bias[n0 + tn * 8 + j];

#pragma unroll
    for (int i = 0; i < 8; i++) {
        int gm = m0 + tm * 8 + i;
        if (gm >= M) continue;
        int crow = rowmap ? rowmap[gm] : gm;
        float* cptr = C + (size_t)crow * N + n0 + tn * 8;
        float4 v0, v1;
        v0.x = tanhf(acc[i][0] + bv[0]);
        v0.y = tanhf(acc[i][1] + bv[1]);
        v0.z = tanhf(acc[i][2] + bv[2]);
        v0.w = tanhf(acc[i][3] + bv[3]);
        v1.x = tanhf(acc[i][4] + bv[4]);
        v1.y = tanhf(acc[i][5] + bv[5]);
        v1.z = tanhf(acc[i][6] + bv[6]);
        v1.w = tanhf(acc[i][7] + bv[7]);
        *(float4*)(cptr + 0) = v0;
        *(float4*)(cptr + 4) = v1;
    }
}

__global__ void __launch_bounds__(256)
gemm_tanh_plain(const float* __restrict__ A, const float* __restrict__ B,
                const float* __restrict__ bias, float* __restrict__ C,
                int M, int N, int K)
{
    gemm_tanh_body(A, B, bias, C, M, N, K, nullptr, blockIdx.x, blockIdx.y);
}

__global__ void __launch_bounds__(256)
gemm_tanh_expert(const float* __restrict__ ew, const float* __restrict__ eb)
{
    int e   = blockIdx.z;
    int cnt = g_cnt[e];
    if ((int)blockIdx.x * BM >= cnt) return;   // uniform early exit
    gemm_tanh_body(g_x1,
                   ew + (size_t)e * DH * DH,
                   eb + (size_t)e * DH,
                   g_x2,
                   cnt, DH, DH,
                   g_rows + g_off[e],
                   blockIdx.x, blockIdx.y);
}

extern "C" void kernel_launch(void* const* d_in, const int* in_sizes, int n_in,
                              void* d_out, int out_size)
{
    const float* obs    = (const float*)d_in[0];
    const int*   sw     = (const int*)  d_in[1];
    const float* pre_w  = (const float*)d_in[2];
    const float* pre_b  = (const float*)d_in[3];
    const float* exp_w  = (const float*)d_in[4];
    const float* exp_b  = (const float*)d_in[5];
    const float* post_w = (const float*)d_in[6];
    const float* post_b = (const float*)d_in[7];
    float*       out    = (float*)d_out;

    float* x1 = nullptr;
    float* x2 = nullptr;
    cudaGetSymbolAddress((void**)&x1, g_x1);
    cudaGetSymbolAddress((void**)&x2, g_x2);

    // Grouping (independent of stage 1; tiny)
    group_kernel<<<1, 256>>>(sw);

    // Stage 1: x1 = tanh(obs @ pre_w^T + pre_b)   [4096, 2048]
    gemm_tanh_plain<<<dim3(BATCH / BM, DH / BN), 256>>>(
        obs, pre_w, pre_b, x1, BATCH, DH, DIN);

    // Stage 2: grouped expert GEMM, x2[b] = tanh(x1[b] @ W_e^T + b_e)
    gemm_tanh_expert<<<dim3(BATCH / BM, DH / BN, NEXP), 256>>>(exp_w, exp_b);

    // Stage 3: out = tanh(x2 @ post_w^T + post_b)  [4096, 1024]
    gemm_tanh_plain<<<dim3(BATCH / BM, DOUT / BN), 256>>>(
        x2, post_w, post_b, out, BATCH, DOUT, DH);
}

// round 4
// speedup vs baseline: 1.4708x; 1.4708x over previous
#include <cuda_runtime.h>
#include <cuda_bf16.h>
#include <math.h>
#include <stdint.h>

// Problem constants
#define BATCH 4096
#define DIN   1024
#define DH    2048
#define DOUT  1024
#define NEXP  16

// Tiling
#define BM 128
#define BN 128
#define BK 32
#define NSTAGE 3
#define ROWF 36                        // padded row stride in floats (144B, 16B-aligned)
#define TILEF (128 * ROWF)             // floats per A (or B) tile
#define STAGEF (2 * TILEF)             // floats per stage (A + B)
#define DYNSMEM (NSTAGE * STAGEF * 4)  // bytes

// Scratch (device globals — no allocation allowed)
__device__ float g_x1[BATCH * DH];   // grouped-order tanh(obs @ pre_w^T + pre_b)
__device__ float g_x2[BATCH * DH];   // grouped-order tanh(expert out)
__device__ int   g_rows[BATCH];      // grouped position p -> original batch row
__device__ int   g_pos [BATCH];      // original batch row -> grouped position p
__device__ int   g_cnt[NEXP];
__device__ int   g_off[NEXP];

// ---------------------------------------------------------------------------
__device__ __forceinline__ uint32_t smem_u32(const void* p) {
    uint32_t a;
    asm("{ .reg .u64 t; cvta.to.shared.u64 t, %1; cvt.u32.u64 %0, t; }"
        : "=r"(a) : "l"(p));
    return a;
}

__device__ __forceinline__ void cp_async16(uint32_t smem, const void* g) {
    asm volatile("cp.async.cg.shared.global [%0], [%1], 16;" :: "r"(smem), "l"(g) : "memory");
}
__device__ __forceinline__ void cp_commit() {
    asm volatile("cp.async.commit_group;" ::: "memory");
}
__device__ __forceinline__ void cp_wait1() {
    asm volatile("cp.async.wait_group 1;" ::: "memory");
}

__device__ __forceinline__ void mma_tf32(float* c, const uint32_t* a, const uint32_t* b) {
    asm volatile(
        "mma.sync.aligned.m16n8k8.row.col.f32.tf32.tf32.f32 "
        "{%0,%1,%2,%3}, {%4,%5,%6,%7}, {%8,%9}, {%0,%1,%2,%3};"
        : "+f"(c[0]), "+f"(c[1]), "+f"(c[2]), "+f"(c[3])
        : "r"(a[0]), "r"(a[1]), "r"(a[2]), "r"(a[3]), "r"(b[0]), "r"(b[1]));
}

// Split fp32 -> (hi, lo) tf32 pair:  x ≈ hi + lo, |lo| <= 2^-11 |x|
__device__ __forceinline__ void split_tf32(float x, uint32_t& hi, uint32_t& lo) {
    uint32_t h;
    asm("cvt.rna.tf32.f32 %0, %1;" : "=r"(h) : "f"(x));
    float r = x - __uint_as_float(h);
    uint32_t l;
    asm("cvt.rna.tf32.f32 %0, %1;" : "=r"(l) : "f"(r));
    hi = h;
    lo = l;
}

// ---------------------------------------------------------------------------
// Group rows by expert index; forward (g_rows) and inverse (g_pos) maps.
// ---------------------------------------------------------------------------
__global__ void group_kernel(const int* __restrict__ idx)
{
    __shared__ int s_cnt[NEXP];
    __shared__ int s_off[NEXP];
    __shared__ int s_fill[NEXP];
    int t = threadIdx.x;
    if (t < NEXP) s_cnt[t] = 0;
    __syncthreads();
    for (int b = t; b < BATCH; b += blockDim.x)
        atomicAdd(&s_cnt[idx[b]], 1);
    __syncthreads();
    if (t == 0) {
        int acc = 0;
        for (int e = 0; e < NEXP; e++) {
            s_off[e]  = acc;
            acc      += s_cnt[e];
            s_fill[e] = 0;
        }
    }
    __syncthreads();
    for (int b = t; b < BATCH; b += blockDim.x) {
        int e = idx[b];
        int p = s_off[e] + atomicAdd(&s_fill[e], 1);
        g_rows[p] = b;
        g_pos[b]  = p;
    }
    if (t < NEXP) { g_cnt[t] = s_cnt[t]; g_off[t] = s_off[t]; }
}

// ---------------------------------------------------------------------------
// 3xTF32 tensor-core GEMM with fused bias + tanh:  C = tanh(A @ B^T + bias)
// MODE 0: stage 1 — A rows direct, C row = g_pos[m]  (scatter into grouped)
// MODE 1: stage 2 — grouped expert GEMM (A rows = g_off[e]+m contiguous)
// MODE 2: stage 3 — A rows grouped, C row = g_rows[m] (scatter back)
// 256 threads: 8 warps, each computes a 64x32 warp tile of the 128x128 CTA tile.
// ---------------------------------------------------------------------------
template<int MODE>
__global__ void __launch_bounds__(256, 1)
gemm_mma(const float* __restrict__ A, const float* __restrict__ Bw,
         const float* __restrict__ bias, float* __restrict__ C,
         int N, int K)
{
    const int e  = (MODE == 1) ? blockIdx.z : 0;
    const int Mv = (MODE == 1) ? g_cnt[e] : BATCH;
    const int m0 = blockIdx.x * BM;
    if (m0 >= Mv) return;
    const int n0    = blockIdx.y * BN;
    const int abase = (MODE == 1) ? g_off[e] + m0 : m0;
    const float* Bp = (MODE == 1) ? Bw + (size_t)e * DH * DH : Bw;
    const float* bp = (MODE == 1) ? bias + (size_t)e * DH : bias;

    extern __shared__ float smf[];
    const uint32_t smu = smem_u32(smf);

    const int tid  = threadIdx.x;
    const int lane = tid & 31;
    const int warp = tid >> 5;
    const int wm   = (warp & 1) * 64;   // warp-tile m offset within CTA tile
    const int wn   = (warp >> 1) * 32;  // warp-tile n offset

    // ---- global load coordinates: 4 x 16B chunks each for A and B ----
    const float* ga[4];
    const float* gb[4];
    uint32_t soff[4];
#pragma unroll
    for (int l = 0; l < 4; l++) {
        int ch = tid + l * 256;
        int r  = ch >> 3;
        int c  = ch & 7;
        int ar = abase + r;
        if (MODE == 1) ar = (ar < BATCH) ? ar : (BATCH - 1);
        ga[l]  = A  + (size_t)ar * K + c * 4;
        gb[l]  = Bp + (size_t)(n0 + r) * K + c * 4;
        soff[l] = (uint32_t)r * (ROWF * 4) + (uint32_t)c * 16;
    }

    const int KT = K / BK;

    // ---- prologue: stages 0 and 1 ----
#pragma unroll
    for (int s = 0; s < 2; s++) {
        const uint32_t sa = smu + s * (STAGEF * 4);
        const uint32_t sb = sa + TILEF * 4;
        const int ko = s * BK;
#pragma unroll
        for (int l = 0; l < 4; l++) {
            cp_async16(sa + soff[l], ga[l] + ko);
            cp_async16(sb + soff[l], gb[l] + ko);
        }
        cp_commit();
    }

    float acc[4][4][4];
#pragma unroll
    for (int i = 0; i < 4; i++)
#pragma unroll
        for (int j = 0; j < 4; j++)
#pragma unroll
            for (int r = 0; r < 4; r++) acc[i][j][r] = 0.0f;

    const int lr = lane >> 2;   // 0..7
    const int lc = lane & 3;    // 0..3

    int sbuf = 0;
    for (int kt = 0; kt < KT; kt++) {
        cp_wait1();
        __syncthreads();

        // issue loads for stage kt+2
        if (kt + 2 < KT) {
            int snext = sbuf + 2; if (snext >= NSTAGE) snext -= NSTAGE;
            const uint32_t sa = smu + snext * (STAGEF * 4);
            const uint32_t sb = sa + TILEF * 4;
            const int ko = (kt + 2) * BK;
#pragma unroll
            for (int l = 0; l < 4; l++) {
                cp_async16(sa + soff[l], ga[l] + ko);
                cp_async16(sb + soff[l], gb[l] + ko);
            }
        }
        cp_commit();

        // ---- compute on stage sbuf (3xTF32: hi/lo split, 3 MMAs per pair) ----
        const float* As = smf + sbuf * STAGEF;
        const float* Bs = As + TILEF;
#pragma unroll
        for (int ks = 0; ks < 4; ks++) {
            const int kb = ks * 8;
            uint32_t ah[4][4], al[4][4], bh[4][2], bl[4][2];
#pragma unroll
            for (int mf = 0; mf < 4; mf++) {
                const int m = wm + mf * 16 + lr;
                split_tf32(As[m * ROWF + kb + lc],           ah[mf][0], al[mf][0]);
                split_tf32(As[(m + 8) * ROWF + kb + lc],     ah[mf][1], al[mf][1]);
                split_tf32(As[m * ROWF + kb + lc + 4],       ah[mf][2], al[mf][2]);
                split_tf32(As[(m + 8) * ROWF + kb + lc + 4], ah[mf][3], al[mf][3]);
            }
#pragma unroll
            for (int nf = 0; nf < 4; nf++) {
                const int n = wn + nf * 8 + lr;
                split_tf32(Bs[n * ROWF + kb + lc],     bh[nf][0], bl[nf][0]);
                split_tf32(Bs[n * ROWF + kb + lc + 4], bh[nf][1], bl[nf][1]);
            }
#pragma unroll
            for (int mf = 0; mf < 4; mf++)
#pragma unroll
                for (int nf = 0; nf < 4; nf++) {
                    mma_tf32(acc[mf][nf], al[mf], bh[nf]);   // a_lo * b_hi
                    mma_tf32(acc[mf][nf], ah[mf], bl[nf]);   // a_hi * b_lo
                    mma_tf32(acc[mf][nf], ah[mf], bh[nf]);   // a_hi * b_hi
                }
        }
        __syncthreads();
        if (++sbuf == NSTAGE) sbuf = 0;
    }

    // ---- epilogue: bias + tanh + scattered store ----
    float2 bv[4];
#pragma unroll
    for (int nf = 0; nf < 4; nf++) {
        const int c = n0 + wn + nf * 8 + 2 * lc;
        bv[nf].x = bp[c];
        bv[nf].y = bp[c + 1];
    }

#pragma unroll
    for (int mf = 0; mf < 4; mf++) {
#pragma unroll
        for (int half = 0; half < 2; half++) {
            const int gm = m0 + wm + mf * 16 + lr + half * 8;
            if (gm >= Mv) continue;
            int crow;
            if      (MODE == 0) crow = g_pos[gm];
            else if (MODE == 1) crow = (abase - m0) + gm;   // g_off[e] + local
            else                crow = g_rows[gm];
            float* cp = C + (size_t)crow * N + n0 + wn + 2 * lc;
#pragma unroll
            for (int nf = 0; nf < 4; nf++) {
                float2 v;
                v.x = tanhf(acc[mf][nf][half * 2 + 0] + bv[nf].x);
                v.y = tanhf(acc[mf][nf][half * 2 + 1] + bv[nf].y);
                *(float2*)(cp + nf * 8) = v;
            }
        }
    }
}

// ---------------------------------------------------------------------------
extern "C" void kernel_launch(void* const* d_in, const int* in_sizes, int n_in,
                              void* d_out, int out_size)
{
    const float* obs    = (const float*)d_in[0];
    const int*   sw     = (const int*)  d_in[1];
    const float* pre_w  = (const float*)d_in[2];
    const float* pre_b  = (const float*)d_in[3];
    const float* exp_w  = (const float*)d_in[4];
    const float* exp_b  = (const float*)d_in[5];
    const float* post_w = (const float*)d_in[6];
    const float* post_b = (const float*)d_in[7];
    float*       out    = (float*)d_out;

    float* x1 = nullptr;
    float* x2 = nullptr;
    cudaGetSymbolAddress((void**)&x1, g_x1);
    cudaGetSymbolAddress((void**)&x2, g_x2);

    cudaFuncSetAttribute((const void*)gemm_mma<0>,
                         cudaFuncAttributeMaxDynamicSharedMemorySize, DYNSMEM);
    cudaFuncSetAttribute((const void*)gemm_mma<1>,
                         cudaFuncAttributeMaxDynamicSharedMemorySize, DYNSMEM);
    cudaFuncSetAttribute((const void*)gemm_mma<2>,
                         cudaFuncAttributeMaxDynamicSharedMemorySize, DYNSMEM);

    group_kernel<<<1, 256>>>(sw);

    // Stage 1: x1[g_pos[b]] = tanh(obs[b] @ pre_w^T + pre_b)
    gemm_mma<0><<<dim3(BATCH / BM, DH / BN), 256, DYNSMEM>>>(
        obs, pre_w, pre_b, x1, DH, DIN);

    // Stage 2: per-expert dense GEMM over contiguous grouped rows
    gemm_mma<1><<<dim3(BATCH / BM, DH / BN, NEXP), 256, DYNSMEM>>>(
        x1, exp_w, exp_b, x2, DH, DH);

    // Stage 3: out[g_rows[p]] = tanh(x2[p] @ post_w^T + post_b)
    gemm_mma<2><<<dim3(BATCH / BM, DOUT / BN), 256, DYNSMEM>>>(
        x2, post_w, post_b, out, DOUT, DH);
}

// round 5
// speedup vs baseline: 2.2434x; 1.5252x over previous
#include <cuda_runtime.h>
#include <cuda_bf16.h>
#include <cuda_fp16.h>
#include <math.h>
#include <stdint.h>

// Problem constants
#define BATCH 4096
#define DIN   1024
#define DH    2048
#define DOUT  1024
#define NEXP  16

// Tiling
#define BM 128
#define BN 128
#define BK 32
#define NSTAGE 3
#define ROWF 36                        // padded row stride in floats (144B, 16B-aligned)
#define TILEF (128 * ROWF)             // floats per A (or B) tile
#define STAGEF (2 * TILEF)             // floats per stage (A + B)
#define DYNSMEM (NSTAGE * STAGEF * 4)  // bytes

// Scratch (device globals — no allocation allowed)
__device__ float g_x1[BATCH * DH];   // grouped-order tanh(obs @ pre_w^T + pre_b)
__device__ float g_x2[BATCH * DH];   // grouped-order tanh(expert out)
__device__ int   g_rows[BATCH];      // grouped position p -> original batch row
__device__ int   g_pos [BATCH];      // original batch row -> grouped position p
__device__ int   g_cnt[NEXP];
__device__ int   g_off[NEXP];

// ---------------------------------------------------------------------------
__device__ __forceinline__ uint32_t smem_u32(const void* p) {
    uint32_t a;
    asm("{ .reg .u64 t; cvta.to.shared.u64 t, %1; cvt.u32.u64 %0, t; }"
        : "=r"(a) : "l"(p));
    return a;
}

__device__ __forceinline__ void cp_async16(uint32_t smem, const void* g) {
    asm volatile("cp.async.cg.shared.global [%0], [%1], 16;" :: "r"(smem), "l"(g) : "memory");
}
__device__ __forceinline__ void cp_commit() {
    asm volatile("cp.async.commit_group;" ::: "memory");
}
__device__ __forceinline__ void cp_wait1() {
    asm volatile("cp.async.wait_group 1;" ::: "memory");
}

__device__ __forceinline__ void mma_f16(float* c, const uint32_t* a, const uint32_t* b) {
    asm volatile(
        "mma.sync.aligned.m16n8k16.row.col.f32.f16.f16.f32 "
        "{%0,%1,%2,%3}, {%4,%5,%6,%7}, {%8,%9}, {%0,%1,%2,%3};"
        : "+f"(c[0]), "+f"(c[1]), "+f"(c[2]), "+f"(c[3])
        : "r"(a[0]), "r"(a[1]), "r"(a[2]), "r"(a[3]), "r"(b[0]), "r"(b[1]));
}

// Split two adjacent fp32 values into packed fp16 (hi) and packed fp16 residual (lo).
// x ≈ hi + lo with |dropped| ~ 2^-22 |x|.
__device__ __forceinline__ void split_f16x2(const float* p, uint32_t& hi, uint32_t& lo) {
    float2 v = *(const float2*)p;
    __half2 h = __floats2half2_rn(v.x, v.y);
    float2 hf = __half22float2(h);
    __half2 l = __floats2half2_rn(v.x - hf.x, v.y - hf.y);
    hi = *(uint32_t*)&h;
    lo = *(uint32_t*)&l;
}

// ---------------------------------------------------------------------------
// Group rows by expert index; forward (g_rows) and inverse (g_pos) maps.
// ---------------------------------------------------------------------------
__global__ void group_kernel(const int* __restrict__ idx)
{
    __shared__ int s_cnt[NEXP];
    __shared__ int s_off[NEXP];
    __shared__ int s_fill[NEXP];
    int t = threadIdx.x;
    if (t < NEXP) s_cnt[t] = 0;
    __syncthreads();
    for (int b = t; b < BATCH; b += blockDim.x)
        atomicAdd(&s_cnt[idx[b]], 1);
    __syncthreads();
    if (t == 0) {
        int acc = 0;
        for (int e = 0; e < NEXP; e++) {
            s_off[e]  = acc;
            acc      += s_cnt[e];
            s_fill[e] = 0;
        }
    }
    __syncthreads();
    for (int b = t; b < BATCH; b += blockDim.x) {
        int e = idx[b];
        int p = s_off[e] + atomicAdd(&s_fill[e], 1);
        g_rows[p] = b;
        g_pos[b]  = p;
    }
    if (t < NEXP) { g_cnt[t] = s_cnt[t]; g_off[t] = s_off[t]; }
}

// ---------------------------------------------------------------------------
// 3xFP16 tensor-core GEMM with fused bias + tanh:  C = tanh(A @ B^T + bias)
// MODE 0: stage 1 — A rows direct, C row = g_pos[m]  (scatter into grouped)
// MODE 1: stage 2 — grouped expert GEMM (A rows = g_off[e]+m contiguous)
// MODE 2: stage 3 — A rows grouped, C row = g_rows[m] (scatter back)
// 256 threads: 8 warps, each computes a 64x32 warp tile of the 128x128 CTA tile.
// ---------------------------------------------------------------------------
template<int MODE>
__global__ void __launch_bounds__(256, 1)
gemm_mma(const float* __restrict__ A, const float* __restrict__ Bw,
         const float* __restrict__ bias, float* __restrict__ C,
         int N, int K)
{
    const int e  = (MODE == 1) ? blockIdx.z : 0;
    const int Mv = (MODE == 1) ? g_cnt[e] : BATCH;
    const int m0 = blockIdx.x * BM;
    if (m0 >= Mv) return;
    const int n0    = blockIdx.y * BN;
    const int abase = (MODE == 1) ? g_off[e] + m0 : m0;
    const float* Bp = (MODE == 1) ? Bw + (size_t)e * DH * DH : Bw;
    const float* bp = (MODE == 1) ? bias + (size_t)e * DH : bias;

    extern __shared__ float smf[];
    const uint32_t smu = smem_u32(smf);

    const int tid  = threadIdx.x;
    const int lane = tid & 31;
    const int warp = tid >> 5;
    const int wm   = (warp & 1) * 64;   // warp-tile m offset within CTA tile
    const int wn   = (warp >> 1) * 32;  // warp-tile n offset

    // ---- global load coordinates: 4 x 16B chunks each for A and B ----
    const float* ga[4];
    const float* gb[4];
    uint32_t soff[4];
#pragma unroll
    for (int l = 0; l < 4; l++) {
        int ch = tid + l * 256;
        int r  = ch >> 3;
        int c  = ch & 7;
        int ar = abase + r;
        if (MODE == 1) ar = (ar < BATCH) ? ar : (BATCH - 1);
        ga[l]  = A  + (size_t)ar * K + c * 4;
        gb[l]  = Bp + (size_t)(n0 + r) * K + c * 4;
        soff[l] = (uint32_t)r * (ROWF * 4) + (uint32_t)c * 16;
    }

    const int KT = K / BK;

    // ---- prologue: stages 0 and 1 ----
#pragma unroll
    for (int s = 0; s < 2; s++) {
        const uint32_t sa = smu + s * (STAGEF * 4);
        const uint32_t sb = sa + TILEF * 4;
        const int ko = s * BK;
#pragma unroll
        for (int l = 0; l < 4; l++) {
            cp_async16(sa + soff[l], ga[l] + ko);
            cp_async16(sb + soff[l], gb[l] + ko);
        }
        cp_commit();
    }

    float acc[4][4][4];
#pragma unroll
    for (int i = 0; i < 4; i++)
#pragma unroll
        for (int j = 0; j < 4; j++)
#pragma unroll
            for (int r = 0; r < 4; r++) acc[i][j][r] = 0.0f;

    const int lr = lane >> 2;   // 0..7
    const int lc = lane & 3;    // 0..3

    int sbuf = 0;
    for (int kt = 0; kt < KT; kt++) {
        cp_wait1();
        __syncthreads();

        // issue loads for stage kt+2
        if (kt + 2 < KT) {
            int snext = sbuf + 2; if (snext >= NSTAGE) snext -= NSTAGE;
            const uint32_t sa = smu + snext * (STAGEF * 4);
            const uint32_t sb = sa + TILEF * 4;
            const int ko = (kt + 2) * BK;
#pragma unroll
            for (int l = 0; l < 4; l++) {
                cp_async16(sa + soff[l], ga[l] + ko);
                cp_async16(sb + soff[l], gb[l] + ko);
            }
        }
        cp_commit();

        // ---- compute on stage sbuf: 3xFP16 hi/lo split, product-major order ----
        const float* As = smf + sbuf * STAGEF;
        const float* Bs = As + TILEF;
#pragma unroll
        for (int ks = 0; ks < BK / 16; ks++) {
            const int kb = ks * 16;
            uint32_t ah[4][4], al[4][4], bh[4][2], bl[4][2];
#pragma unroll
            for (int mf = 0; mf < 4; mf++) {
                const int m = wm + mf * 16 + lr;
                split_f16x2(&As[m * ROWF + kb + 2 * lc],           ah[mf][0], al[mf][0]);
                split_f16x2(&As[(m + 8) * ROWF + kb + 2 * lc],     ah[mf][1], al[mf][1]);
                split_f16x2(&As[m * ROWF + kb + 2 * lc + 8],       ah[mf][2], al[mf][2]);
                split_f16x2(&As[(m + 8) * ROWF + kb + 2 * lc + 8], ah[mf][3], al[mf][3]);
            }
#pragma unroll
            for (int nf = 0; nf < 4; nf++) {
                const int n = wn + nf * 8 + lr;
                split_f16x2(&Bs[n * ROWF + kb + 2 * lc],     bh[nf][0], bl[nf][0]);
                split_f16x2(&Bs[n * ROWF + kb + 2 * lc + 8], bh[nf][1], bl[nf][1]);
            }
            // product-major: 16 independent MMAs between writes to the same acc
#pragma unroll
            for (int mf = 0; mf < 4; mf++)
#pragma unroll
                for (int nf = 0; nf < 4; nf++)
                    mma_f16(acc[mf][nf], al[mf], bh[nf]);   // a_lo * b_hi
#pragma unroll
            for (int mf = 0; mf < 4; mf++)
#pragma unroll
                for (int nf = 0; nf < 4; nf++)
                    mma_f16(acc[mf][nf], ah[mf], bl[nf]);   // a_hi * b_lo
#pragma unroll
            for (int mf = 0; mf < 4; mf++)
#pragma unroll
                for (int nf = 0; nf < 4; nf++)
                    mma_f16(acc[mf][nf], ah[mf], bh[nf]);   // a_hi * b_hi
        }
        __syncthreads();
        if (++sbuf == NSTAGE) sbuf = 0;
    }

    // ---- epilogue: bias + tanh + scattered store ----
    float2 bv[4];
#pragma unroll
    for (int nf = 0; nf < 4; nf++) {
        const int c = n0 + wn + nf * 8 + 2 * lc;
        bv[nf].x = bp[c];
        bv[nf].y = bp[c + 1];
    }

#pragma unroll
    for (int mf = 0; mf < 4; mf++) {
#pragma unroll
        for (int half = 0; half < 2; half++) {
            const int gm = m0 + wm + mf * 16 + lr + half * 8;
            if (gm >= Mv) continue;
            int crow;
            if      (MODE == 0) crow = g_pos[gm];
            else if (MODE == 1) crow = (abase - m0) + gm;   // g_off[e] + local
            else                crow = g_rows[gm];
            float* cp = C + (size_t)crow * N + n0 + wn + 2 * lc;
#pragma unroll
            for (int nf = 0; nf < 4; nf++) {
                float2 v;
                v.x = tanhf(acc[mf][nf][half * 2 + 0] + bv[nf].x);
                v.y = tanhf(acc[mf][nf][half * 2 + 1] + bv[nf].y);
                *(float2*)(cp + nf * 8) = v;
            }
        }
    }
}

// ---------------------------------------------------------------------------
extern "C" void kernel_launch(void* const* d_in, const int* in_sizes, int n_in,
                              void* d_out, int out_size)
{
    const float* obs    = (const float*)d_in[0];
    const int*   sw     = (const int*)  d_in[1];
    const float* pre_w  = (const float*)d_in[2];
    const float* pre_b  = (const float*)d_in[3];
    const float* exp_w  = (const float*)d_in[4];
    const float* exp_b  = (const float*)d_in[5];
    const float* post_w = (const float*)d_in[6];
    const float* post_b = (const float*)d_in[7];
    float*       out    = (float*)d_out;

    float* x1 = nullptr;
    float* x2 = nullptr;
    cudaGetSymbolAddress((void**)&x1, g_x1);
    cudaGetSymbolAddress((void**)&x2, g_x2);

    cudaFuncSetAttribute((const void*)gemm_mma<0>,
                         cudaFuncAttributeMaxDynamicSharedMemorySize, DYNSMEM);
    cudaFuncSetAttribute((const void*)gemm_mma<1>,
                         cudaFuncAttributeMaxDynamicSharedMemorySize, DYNSMEM);
    cudaFuncSetAttribute((const void*)gemm_mma<2>,
                         cudaFuncAttributeMaxDynamicSharedMemorySize, DYNSMEM);

    group_kernel<<<1, 256>>>(sw);

    // Stage 1: x1[g_pos[b]] = tanh(obs[b] @ pre_w^T + pre_b)
    gemm_mma<0><<<dim3(BATCH / BM, DH / BN), 256, DYNSMEM>>>(
        obs, pre_w, pre_b, x1, DH, DIN);

    // Stage 2: per-expert dense GEMM over contiguous grouped rows
    gemm_mma<1><<<dim3(BATCH / BM, DH / BN, NEXP), 256, DYNSMEM>>>(
        x1, exp_w, exp_b, x2, DH, DH);

    // Stage 3: out[g_rows[p]] = tanh(x2[p] @ post_w^T + post_b)
    gemm_mma<2><<<dim3(BATCH / BM, DOUT / BN), 256, DYNSMEM>>>(
        x2, post_w, post_b, out, DOUT, DH);
}

// round 6
// speedup vs baseline: 2.4714x; 1.1017x over previous
#include <cuda_runtime.h>
#include <cuda_bf16.h>
#include <cuda_fp16.h>
#include <math.h>
#include <stdint.h>

// Problem constants
#define BATCH 4096
#define DIN   1024
#define DH    2048
#define DOUT  1024
#define NEXP  16

// Tiling
#define BM 128
#define BN 128
#define BK 32                 // k-halfs per stage
#define NSTAGE 3
#define ROWH 40               // padded row stride in halfs (80B) -> conflict-free
#define TILEB (128 * ROWH * 2)            // 10240 bytes per matrix tile
#define AH_OFF 0
#define AL_OFF (1 * TILEB)
#define BH_OFF (2 * TILEB)
#define BL_OFF (3 * TILEB)
#define STAGEB (4 * TILEB)                // 40960
#define DYNSMEM (NSTAGE * STAGEB)         // 122880

// Scratch (device globals — no allocation allowed)
__device__ __half g_obs_h[BATCH * DIN],  g_obs_l[BATCH * DIN];
__device__ __half g_prew_h[DH * DIN],    g_prew_l[DH * DIN];
__device__ __half g_expw_h[NEXP * DH * DH], g_expw_l[NEXP * DH * DH];
__device__ __half g_postw_h[DOUT * DH],  g_postw_l[DOUT * DH];
__device__ __half g_x1_h[BATCH * DH],    g_x1_l[BATCH * DH];
__device__ __half g_x2_h[BATCH * DH],    g_x2_l[BATCH * DH];
__device__ int   g_rows[BATCH];      // grouped position p -> original batch row
__device__ int   g_pos [BATCH];      // original batch row -> grouped position p
__device__ int   g_cnt[NEXP];
__device__ int   g_off[NEXP];

// ---------------------------------------------------------------------------
__device__ __forceinline__ uint32_t smem_u32(const void* p) {
    uint32_t a;
    asm("{ .reg .u64 t; cvta.to.shared.u64 t, %1; cvt.u32.u64 %0, t; }"
        : "=r"(a) : "l"(p));
    return a;
}

__device__ __forceinline__ void cp_async16(uint32_t smem, const void* g) {
    asm volatile("cp.async.cg.shared.global [%0], [%1], 16;" :: "r"(smem), "l"(g) : "memory");
}
__device__ __forceinline__ void cp_commit() {
    asm volatile("cp.async.commit_group;" ::: "memory");
}
__device__ __forceinline__ void cp_wait1() {
    asm volatile("cp.async.wait_group 1;" ::: "memory");
}

__device__ __forceinline__ void ldsm4(uint32_t* r, uint32_t addr) {
    asm volatile("ldmatrix.sync.aligned.m8n8.x4.shared.b16 {%0,%1,%2,%3}, [%4];"
        : "=r"(r[0]), "=r"(r[1]), "=r"(r[2]), "=r"(r[3]) : "r"(addr));
}

__device__ __forceinline__ void mma_f16(float* c, const uint32_t* a, const uint32_t* b) {
    asm volatile(
        "mma.sync.aligned.m16n8k16.row.col.f32.f16.f16.f32 "
        "{%0,%1,%2,%3}, {%4,%5,%6,%7}, {%8,%9}, {%0,%1,%2,%3};"
        : "+f"(c[0]), "+f"(c[1]), "+f"(c[2]), "+f"(c[3])
        : "r"(a[0]), "r"(a[1]), "r"(a[2]), "r"(a[3]), "r"(b[0]), "r"(b[1]));
}

// ---------------------------------------------------------------------------
// Split fp32 buffer into fp16 hi + fp16 residual lo (4 floats per thread).
// ---------------------------------------------------------------------------
__global__ void split_kernel(const float* __restrict__ src,
                             __half* __restrict__ hi, __half* __restrict__ lo,
                             int n4)
{
    int i = blockIdx.x * blockDim.x + threadIdx.x;
    if (i >= n4) return;
    float4 v = ((const float4*)src)[i];
    __half2 h0 = __floats2half2_rn(v.x, v.y);
    __half2 h1 = __floats2half2_rn(v.z, v.w);
    float2 f0 = __half22float2(h0);
    float2 f1 = __half22float2(h1);
    __half2 l0 = __floats2half2_rn(v.x - f0.x, v.y - f0.y);
    __half2 l1 = __floats2half2_rn(v.z - f1.x, v.w - f1.y);
    ((uint2*)hi)[i] = make_uint2(*(uint32_t*)&h0, *(uint32_t*)&h1);
    ((uint2*)lo)[i] = make_uint2(*(uint32_t*)&l0, *(uint32_t*)&l1);
}

// ---------------------------------------------------------------------------
// Group rows by expert index; forward (g_rows) and inverse (g_pos) maps.
// ---------------------------------------------------------------------------
__global__ void group_kernel(const int* __restrict__ idx)
{
    __shared__ int s_cnt[NEXP];
    __shared__ int s_off[NEXP];
    __shared__ int s_fill[NEXP];
    int t = threadIdx.x;
    if (t < NEXP) s_cnt[t] = 0;
    __syncthreads();
    for (int b = t; b < BATCH; b += blockDim.x)
        atomicAdd(&s_cnt[idx[b]], 1);
    __syncthreads();
    if (t == 0) {
        int acc = 0;
        for (int e = 0; e < NEXP; e++) {
            s_off[e]  = acc;
            acc      += s_cnt[e];
            s_fill[e] = 0;
        }
    }
    __syncthreads();
    for (int b = t; b < BATCH; b += blockDim.x) {
        int e = idx[b];
        int p = s_off[e] + atomicAdd(&s_fill[e], 1);
        g_rows[p] = b;
        g_pos[b]  = p;
    }
    if (t < NEXP) { g_cnt[t] = s_cnt[t]; g_off[t] = s_off[t]; }
}

// ---------------------------------------------------------------------------
// 3xFP16 tensor-core GEMM on PRE-SPLIT operands, fused bias + tanh.
//   C = tanh(A @ B^T + bias),  A = Ah+Al, B = Bh+Bl (fp16 hi/lo pairs)
// MODE 0: stage 1 — A rows direct, C row = g_pos[m], C written as hi/lo halves
// MODE 1: stage 2 — grouped expert GEMM, C written as hi/lo halves
// MODE 2: stage 3 — A rows grouped, C row = g_rows[m], C written fp32
// 256 threads: 8 warps, each computes a 64x32 warp tile of the 128x128 CTA tile.
// ---------------------------------------------------------------------------
template<int MODE>
__global__ void __launch_bounds__(256, 1)
gemm_mma(const __half* __restrict__ Ah, const __half* __restrict__ Al,
         const __half* __restrict__ Bwh, const __half* __restrict__ Bwl,
         const float* __restrict__ bias,
         __half* __restrict__ Ch, __half* __restrict__ Cl,
         float* __restrict__ Cf,
         int N, int K)
{
    const int e  = (MODE == 1) ? blockIdx.z : 0;
    const int Mv = (MODE == 1) ? g_cnt[e] : BATCH;
    const int m0 = blockIdx.x * BM;
    if (m0 >= Mv) return;
    const int n0    = blockIdx.y * BN;
    const int abase = (MODE == 1) ? g_off[e] + m0 : m0;
    const __half* Bh = (MODE == 1) ? Bwh + (size_t)e * DH * DH : Bwh;
    const __half* Bl = (MODE == 1) ? Bwl + (size_t)e * DH * DH : Bwl;
    const float*  bp = (MODE == 1) ? bias + (size_t)e * DH : bias;

    extern __shared__ char smc[];
    const uint32_t smu = smem_u32(smc);

    const int tid  = threadIdx.x;
    const int lane = tid & 31;
    const int warp = tid >> 5;
    const int wm   = (warp & 1) * 64;   // warp-tile m offset
    const int wn   = (warp >> 1) * 32;  // warp-tile n offset

    // ---- cp.async coordinates: 2 chunks (16B) per thread per tile ----
    const __half* gah[2];
    const __half* gal[2];
    const __half* gbh[2];
    const __half* gbl[2];
    uint32_t soff[2];
#pragma unroll
    for (int l = 0; l < 2; l++) {
        int ch = tid + l * 256;
        int r  = ch >> 2;          // 0..127
        int c  = ch & 3;           // 16B chunk within 64B row data
        int ar = abase + r;
        if (MODE == 1) ar = (ar < BATCH) ? ar : (BATCH - 1);
        gah[l] = Ah + (size_t)ar * K + c * 8;
        gal[l] = Al + (size_t)ar * K + c * 8;
        gbh[l] = Bh + (size_t)(n0 + r) * K + c * 8;
        gbl[l] = Bl + (size_t)(n0 + r) * K + c * 8;
        soff[l] = (uint32_t)r * (ROWH * 2) + (uint32_t)c * 16;
    }

    const int KT = K / BK;

    // ---- prologue: stages 0 and 1 ----
#pragma unroll
    for (int s = 0; s < 2; s++) {
        const uint32_t sb = smu + s * STAGEB;
        const int ko = s * BK;
#pragma unroll
        for (int l = 0; l < 2; l++) {
            cp_async16(sb + AH_OFF + soff[l], gah[l] + ko);
            cp_async16(sb + AL_OFF + soff[l], gal[l] + ko);
            cp_async16(sb + BH_OFF + soff[l], gbh[l] + ko);
            cp_async16(sb + BL_OFF + soff[l], gbl[l] + ko);
        }
        cp_commit();
    }

    // ---- ldmatrix lane offsets (bytes within a tile) ----
    const int q = lane >> 3;     // 0..3 (8x8 block select)
    const int s8 = lane & 7;
    uint32_t aoff[4], boff[2];
#pragma unroll
    for (int mf = 0; mf < 4; mf++) {
        int row = wm + mf * 16 + (q & 1) * 8 + s8;
        int col = (q >> 1) * 8;
        aoff[mf] = (uint32_t)(row * ROWH + col) * 2;
    }
#pragma unroll
    for (int p = 0; p < 2; p++) {
        int row = wn + p * 16 + (q >> 1) * 8 + s8;
        int col = (q & 1) * 8;
        boff[p] = (uint32_t)(row * ROWH + col) * 2;
    }

    float acc[4][4][4];
#pragma unroll
    for (int i = 0; i < 4; i++)
#pragma unroll
        for (int j = 0; j < 4; j++)
#pragma unroll
            for (int r = 0; r < 4; r++) acc[i][j][r] = 0.0f;

    int sbuf = 0;
    for (int kt = 0; kt < KT; kt++) {
        cp_wait1();
        __syncthreads();

        // issue loads for stage kt+2
        if (kt + 2 < KT) {
            int snext = sbuf + 2; if (snext >= NSTAGE) snext -= NSTAGE;
            const uint32_t sb = smu + snext * STAGEB;
            const int ko = (kt + 2) * BK;
#pragma unroll
            for (int l = 0; l < 2; l++) {
                cp_async16(sb + AH_OFF + soff[l], gah[l] + ko);
                cp_async16(sb + AL_OFF + soff[l], gal[l] + ko);
                cp_async16(sb + BH_OFF + soff[l], gbh[l] + ko);
                cp_async16(sb + BL_OFF + soff[l], gbl[l] + ko);
            }
        }
        cp_commit();

        // ---- compute on stage sbuf: pure ldmatrix + mma ----
        const uint32_t base = smu + sbuf * STAGEB;
#pragma unroll
        for (int ks = 0; ks < BK / 16; ks++) {
            const uint32_t kb2 = (uint32_t)ks * 32;   // 16 halfs = 32 bytes
            uint32_t ah[4][4], al[4][4], bhv[2][4], blv[2][4];
#pragma unroll
            for (int mf = 0; mf < 4; mf++) {
                ldsm4(ah[mf], base + AH_OFF + aoff[mf] + kb2);
                ldsm4(al[mf], base + AL_OFF + aoff[mf] + kb2);
            }
#pragma unroll
            for (int p = 0; p < 2; p++) {
                ldsm4(bhv[p], base + BH_OFF + boff[p] + kb2);
                ldsm4(blv[p], base + BL_OFF + boff[p] + kb2);
            }
            // product-major: 16 independent MMAs per group
#pragma unroll
            for (int mf = 0; mf < 4; mf++)
#pragma unroll
                for (int nf = 0; nf < 4; nf++)
                    mma_f16(acc[mf][nf], al[mf], &bhv[nf >> 1][(nf & 1) * 2]);
#pragma unroll
            for (int mf = 0; mf < 4; mf++)
#pragma unroll
                for (int nf = 0; nf < 4; nf++)
                    mma_f16(acc[mf][nf], ah[mf], &blv[nf >> 1][(nf & 1) * 2]);
#pragma unroll
            for (int mf = 0; mf < 4; mf++)
#pragma unroll
                for (int nf = 0; nf < 4; nf++)
                    mma_f16(acc[mf][nf], ah[mf], &bhv[nf >> 1][(nf & 1) * 2]);
        }
        __syncthreads();
        if (++sbuf == NSTAGE) sbuf = 0;
    }

    // ---- epilogue: bias + tanh + store (hi/lo halves or fp32) ----
    const int lr = lane >> 2;
    const int lc = lane & 3;
    float2 bv[4];
#pragma unroll
    for (int nf = 0; nf < 4; nf++) {
        const int c = n0 + wn + nf * 8 + 2 * lc;
        bv[nf].x = bp[c];
        bv[nf].y = bp[c + 1];
    }

#pragma unroll
    for (int mf = 0; mf < 4; mf++) {
#pragma unroll
        for (int half = 0; half < 2; half++) {
            const int gm = m0 + wm + mf * 16 + lr + half * 8;
            if (gm >= Mv) continue;
            int crow;
            if      (MODE == 0) crow = g_pos[gm];
            else if (MODE == 1) crow = (abase - m0) + gm;
            else                crow = g_rows[gm];
            const size_t cb = (size_t)crow * N + n0 + wn + 2 * lc;
#pragma unroll
            for (int nf = 0; nf < 4; nf++) {
                float vx = tanhf(acc[mf][nf][half * 2 + 0] + bv[nf].x);
                float vy = tanhf(acc[mf][nf][half * 2 + 1] + bv[nf].y);
                if (MODE == 2) {
                    *(float2*)(Cf + cb + nf * 8) = make_float2(vx, vy);
                } else {
                    __half2 h = __floats2half2_rn(vx, vy);
                    float2 hf = __half22float2(h);
                    __half2 l = __floats2half2_rn(vx - hf.x, vy - hf.y);
                    *(__half2*)(Ch + cb + nf * 8) = h;
                    *(__half2*)(Cl + cb + nf * 8) = l;
                }
            }
        }
    }
}

// ---------------------------------------------------------------------------
extern "C" void kernel_launch(void* const* d_in, const int* in_sizes, int n_in,
                              void* d_out, int out_size)
{
    const float* obs    = (const float*)d_in[0];
    const int*   sw     = (const int*)  d_in[1];
    const float* pre_w  = (const float*)d_in[2];
    const float* pre_b  = (const float*)d_in[3];
    const float* exp_w  = (const float*)d_in[4];
    const float* exp_b  = (const float*)d_in[5];
    const float* post_w = (const float*)d_in[6];
    const float* post_b = (const float*)d_in[7];
    float*       out    = (float*)d_out;

    __half *obs_h, *obs_l, *prew_h, *prew_l, *expw_h, *expw_l, *postw_h, *postw_l;
    __half *x1_h, *x1_l, *x2_h, *x2_l;
    cudaGetSymbolAddress((void**)&obs_h,  g_obs_h);
    cudaGetSymbolAddress((void**)&obs_l,  g_obs_l);
    cudaGetSymbolAddress((void**)&prew_h, g_prew_h);
    cudaGetSymbolAddress((void**)&prew_l, g_prew_l);
    cudaGetSymbolAddress((void**)&expw_h, g_expw_h);
    cudaGetSymbolAddress((void**)&expw_l, g_expw_l);
    cudaGetSymbolAddress((void**)&postw_h, g_postw_h);
    cudaGetSymbolAddress((void**)&postw_l, g_postw_l);
    cudaGetSymbolAddress((void**)&x1_h, g_x1_h);
    cudaGetSymbolAddress((void**)&x1_l, g_x1_l);
    cudaGetSymbolAddress((void**)&x2_h, g_x2_h);
    cudaGetSymbolAddress((void**)&x2_l, g_x2_l);

    cudaFuncSetAttribute((const void*)gemm_mma<0>,
                         cudaFuncAttributeMaxDynamicSharedMemorySize, DYNSMEM);
    cudaFuncSetAttribute((const void*)gemm_mma<1>,
                         cudaFuncAttributeMaxDynamicSharedMemorySize, DYNSMEM);
    cudaFuncSetAttribute((const void*)gemm_mma<2>,
                         cudaFuncAttributeMaxDynamicSharedMemorySize, DYNSMEM);

    group_kernel<<<1, 256>>>(sw);

    // Pre-split inputs to fp16 hi/lo
    split_kernel<<<(BATCH * DIN / 4 + 255) / 256, 256>>>(obs,    obs_h,  obs_l,  BATCH * DIN / 4);
    split_kernel<<<(DH * DIN / 4 + 255) / 256, 256>>>(pre_w,  prew_h, prew_l, DH * DIN / 4);
    split_kernel<<<(NEXP * DH * DH / 4 + 255) / 256, 256>>>(exp_w, expw_h, expw_l, NEXP * DH * DH / 4);
    split_kernel<<<(DOUT * DH / 4 + 255) / 256, 256>>>(post_w, postw_h, postw_l, DOUT * DH / 4);

    // Stage 1: x1[g_pos[b]] = tanh(obs[b] @ pre_w^T + pre_b)  (writes hi/lo)
    gemm_mma<0><<<dim3(BATCH / BM, DH / BN), 256, DYNSMEM>>>(
        obs_h, obs_l, prew_h, prew_l, pre_b, x1_h, x1_l, nullptr, DH, DIN);

    // Stage 2: grouped expert GEMM (writes hi/lo)
    gemm_mma<1><<<dim3(BATCH / BM, DH / BN, NEXP), 256, DYNSMEM>>>(
        x1_h, x1_l, expw_h, expw_l, exp_b, x2_h, x2_l, nullptr, DH, DH);

    // Stage 3: out[g_rows[p]] = tanh(x2[p] @ post_w^T + post_b)  (fp32 out)
    gemm_mma<2><<<dim3(BATCH / BM, DOUT / BN), 256, DYNSMEM>>>(
        x2_h, x2_l, postw_h, postw_l, post_b, nullptr, nullptr, out, DOUT, DH);
}

// round 7
// speedup vs baseline: 2.6283x; 1.0634x over previous
#include <cuda_runtime.h>
#include <cuda_bf16.h>
#include <cuda_fp16.h>
#include <math.h>
#include <stdint.h>

// Problem constants
#define BATCH 4096
#define DIN   1024
#define DH    2048
#define DOUT  1024
#define NEXP  16

// Tiling
#define BM 128
#define BN 128
#define BK 32                 // k-halfs per stage
#define NSTAGE 3
#define NTHREADS 512
#define ROWH 40               // padded row stride in halfs (80B) -> conflict-free ldmatrix
#define TILEB (128 * ROWH * 2)            // 10240 bytes per matrix tile
#define AH_OFF 0
#define AL_OFF (1 * TILEB)
#define BH_OFF (2 * TILEB)
#define BL_OFF (3 * TILEB)
#define STAGEB (4 * TILEB)                // 40960
#define DYNSMEM (NSTAGE * STAGEB)         // 122880

// Scratch (device globals — no allocation allowed)
__device__ __half g_obs_h[BATCH * DIN],  g_obs_l[BATCH * DIN];
__device__ __half g_prew_h[DH * DIN],    g_prew_l[DH * DIN];
__device__ __half g_expw_h[NEXP * DH * DH], g_expw_l[NEXP * DH * DH];
__device__ __half g_postw_h[DOUT * DH],  g_postw_l[DOUT * DH];
__device__ __half g_x1_h[BATCH * DH],    g_x1_l[BATCH * DH];
__device__ __half g_x2_h[BATCH * DH],    g_x2_l[BATCH * DH];
__device__ int   g_rows[BATCH];      // grouped position p -> original batch row
__device__ int   g_pos [BATCH];      // original batch row -> grouped position p
__device__ int   g_cnt[NEXP];
__device__ int   g_off[NEXP];

// ---------------------------------------------------------------------------
__device__ __forceinline__ uint32_t smem_u32(const void* p) {
    uint32_t a;
    asm("{ .reg .u64 t; cvta.to.shared.u64 t, %1; cvt.u32.u64 %0, t; }"
        : "=r"(a) : "l"(p));
    return a;
}

__device__ __forceinline__ void cp_async16(uint32_t smem, const void* g) {
    asm volatile("cp.async.cg.shared.global [%0], [%1], 16;" :: "r"(smem), "l"(g) : "memory");
}
__device__ __forceinline__ void cp_commit() {
    asm volatile("cp.async.commit_group;" ::: "memory");
}
__device__ __forceinline__ void cp_wait1() {
    asm volatile("cp.async.wait_group 1;" ::: "memory");
}

__device__ __forceinline__ void ldsm4(uint32_t* r, uint32_t addr) {
    asm volatile("ldmatrix.sync.aligned.m8n8.x4.shared.b16 {%0,%1,%2,%3}, [%4];"
        : "=r"(r[0]), "=r"(r[1]), "=r"(r[2]), "=r"(r[3]) : "r"(addr));
}

__device__ __forceinline__ void mma_f16(float* c, const uint32_t* a, const uint32_t* b) {
    asm volatile(
        "mma.sync.aligned.m16n8k16.row.col.f32.f16.f16.f32 "
        "{%0,%1,%2,%3}, {%4,%5,%6,%7}, {%8,%9}, {%0,%1,%2,%3};"
        : "+f"(c[0]), "+f"(c[1]), "+f"(c[2]), "+f"(c[3])
        : "r"(a[0]), "r"(a[1]), "r"(a[2]), "r"(a[3]), "r"(b[0]), "r"(b[1]));
}

// ---------------------------------------------------------------------------
// Split fp32 buffer into fp16 hi + fp16 residual lo (4 floats per thread).
// ---------------------------------------------------------------------------
__global__ void split_kernel(const float* __restrict__ src,
                             __half* __restrict__ hi, __half* __restrict__ lo,
                             int n4)
{
    int i = blockIdx.x * blockDim.x + threadIdx.x;
    if (i >= n4) return;
    float4 v = ((const float4*)src)[i];
    __half2 h0 = __floats2half2_rn(v.x, v.y);
    __half2 h1 = __floats2half2_rn(v.z, v.w);
    float2 f0 = __half22float2(h0);
    float2 f1 = __half22float2(h1);
    __half2 l0 = __floats2half2_rn(v.x - f0.x, v.y - f0.y);
    __half2 l1 = __floats2half2_rn(v.z - f1.x, v.w - f1.y);
    ((uint2*)hi)[i] = make_uint2(*(uint32_t*)&h0, *(uint32_t*)&h1);
    ((uint2*)lo)[i] = make_uint2(*(uint32_t*)&l0, *(uint32_t*)&l1);
}

// ---------------------------------------------------------------------------
// Group rows by expert index; forward (g_rows) and inverse (g_pos) maps.
// ---------------------------------------------------------------------------
__global__ void group_kernel(const int* __restrict__ idx)
{
    __shared__ int s_cnt[NEXP];
    __shared__ int s_off[NEXP];
    __shared__ int s_fill[NEXP];
    int t = threadIdx.x;
    if (t < NEXP) s_cnt[t] = 0;
    __syncthreads();
    for (int b = t; b < BATCH; b += blockDim.x)
        atomicAdd(&s_cnt[idx[b]], 1);
    __syncthreads();
    if (t == 0) {
        int acc = 0;
        for (int e = 0; e < NEXP; e++) {
            s_off[e]  = acc;
            acc      += s_cnt[e];
            s_fill[e] = 0;
        }
    }
    __syncthreads();
    for (int b = t; b < BATCH; b += blockDim.x) {
        int e = idx[b];
        int p = s_off[e] + atomicAdd(&s_fill[e], 1);
        g_rows[p] = b;
        g_pos[b]  = p;
    }
    if (t < NEXP) { g_cnt[t] = s_cnt[t]; g_off[t] = s_off[t]; }
}

// ---------------------------------------------------------------------------
// 3xFP16 tensor-core GEMM on PRE-SPLIT operands, fused bias + tanh.
//   C = tanh(A @ B^T + bias),  A = Ah+Al, B = Bh+Bl (fp16 hi/lo pairs)
// MODE 0: stage 1 — A rows direct, C row = g_pos[m], C written as hi/lo halves
// MODE 1: stage 2 — grouped expert GEMM, C written as hi/lo halves
// MODE 2: stage 3 — A rows grouped, C row = g_rows[m], C written fp32
// 512 threads: 16 warps in a 4x4 grid, each computes a 32x32 warp tile.
// ---------------------------------------------------------------------------
template<int MODE>
__global__ void __launch_bounds__(NTHREADS, 1)
gemm_mma(const __half* __restrict__ Ah, const __half* __restrict__ Al,
         const __half* __restrict__ Bwh, const __half* __restrict__ Bwl,
         const float* __restrict__ bias,
         __half* __restrict__ Ch, __half* __restrict__ Cl,
         float* __restrict__ Cf,
         int N, int K)
{
    const int e  = (MODE == 1) ? blockIdx.z : 0;
    const int Mv = (MODE == 1) ? g_cnt[e] : BATCH;
    const int m0 = blockIdx.x * BM;
    if (m0 >= Mv) return;
    const int n0    = blockIdx.y * BN;
    const int abase = (MODE == 1) ? g_off[e] + m0 : m0;
    const __half* Bh = (MODE == 1) ? Bwh + (size_t)e * DH * DH : Bwh;
    const __half* Bl = (MODE == 1) ? Bwl + (size_t)e * DH * DH : Bwl;
    const float*  bp = (MODE == 1) ? bias + (size_t)e * DH : bias;

    extern __shared__ char smc[];
    const uint32_t smu = smem_u32(smc);

    const int tid  = threadIdx.x;
    const int lane = tid & 31;
    const int warp = tid >> 5;
    const int wm   = (warp & 3) * 32;   // warp-tile m offset (4 warps along M)
    const int wn   = (warp >> 2) * 32;  // warp-tile n offset (4 warps along N)

    // ---- cp.async coordinates: 1 chunk (16B) per thread per tile ----
    const int r  = tid >> 2;          // 0..127
    const int c  = tid & 3;           // 16B chunk within 64B row data
    int ar = abase + r;
    if (MODE == 1) ar = (ar < BATCH) ? ar : (BATCH - 1);
    const __half* gah = Ah + (size_t)ar * K + c * 8;
    const __half* gal = Al + (size_t)ar * K + c * 8;
    const __half* gbh = Bh + (size_t)(n0 + r) * K + c * 8;
    const __half* gbl = Bl + (size_t)(n0 + r) * K + c * 8;
    const uint32_t soff = (uint32_t)r * (ROWH * 2) + (uint32_t)c * 16;

    const int KT = K / BK;

    // ---- prologue: stages 0 and 1 ----
#pragma unroll
    for (int s = 0; s < 2; s++) {
        const uint32_t sb = smu + s * STAGEB;
        const int ko = s * BK;
        cp_async16(sb + AH_OFF + soff, gah + ko);
        cp_async16(sb + AL_OFF + soff, gal + ko);
        cp_async16(sb + BH_OFF + soff, gbh + ko);
        cp_async16(sb + BL_OFF + soff, gbl + ko);
        cp_commit();
    }

    // ---- ldmatrix lane offsets (bytes within a tile) ----
    const int q  = lane >> 3;     // 0..3 (8x8 block select)
    const int s8 = lane & 7;
    uint32_t aoff[2], boff[2];
#pragma unroll
    for (int mf = 0; mf < 2; mf++) {
        int row = wm + mf * 16 + (q & 1) * 8 + s8;
        int col = (q >> 1) * 8;
        aoff[mf] = (uint32_t)(row * ROWH + col) * 2;
    }
#pragma unroll
    for (int p = 0; p < 2; p++) {
        int row = wn + p * 16 + (q >> 1) * 8 + s8;
        int col = (q & 1) * 8;
        boff[p] = (uint32_t)(row * ROWH + col) * 2;
    }

    float acc[2][4][4];
#pragma unroll
    for (int i = 0; i < 2; i++)
#pragma unroll
        for (int j = 0; j < 4; j++)
#pragma unroll
            for (int rr = 0; rr < 4; rr++) acc[i][j][rr] = 0.0f;

    int sbuf = 0;
    for (int kt = 0; kt < KT; kt++) {
        cp_wait1();
        __syncthreads();

        // issue loads for stage kt+2
        if (kt + 2 < KT) {
            int snext = sbuf + 2; if (snext >= NSTAGE) snext -= NSTAGE;
            const uint32_t sb = smu + snext * STAGEB;
            const int ko = (kt + 2) * BK;
            cp_async16(sb + AH_OFF + soff, gah + ko);
            cp_async16(sb + AL_OFF + soff, gal + ko);
            cp_async16(sb + BH_OFF + soff, gbh + ko);
            cp_async16(sb + BL_OFF + soff, gbl + ko);
        }
        cp_commit();

        // ---- compute on stage sbuf: pure ldmatrix + mma ----
        const uint32_t base = smu + sbuf * STAGEB;
#pragma unroll
        for (int ks = 0; ks < BK / 16; ks++) {
            const uint32_t kb2 = (uint32_t)ks * 32;   // 16 halfs = 32 bytes
            uint32_t ah[2][4], al[2][4], bhv[2][4], blv[2][4];
#pragma unroll
            for (int mf = 0; mf < 2; mf++) {
                ldsm4(ah[mf], base + AH_OFF + aoff[mf] + kb2);
                ldsm4(al[mf], base + AL_OFF + aoff[mf] + kb2);
            }
#pragma unroll
            for (int p = 0; p < 2; p++) {
                ldsm4(bhv[p], base + BH_OFF + boff[p] + kb2);
                ldsm4(blv[p], base + BL_OFF + boff[p] + kb2);
            }
            // product-major: 8 independent MMAs per group
#pragma unroll
            for (int mf = 0; mf < 2; mf++)
#pragma unroll
                for (int nf = 0; nf < 4; nf++)
                    mma_f16(acc[mf][nf], al[mf], &bhv[nf >> 1][(nf & 1) * 2]);
#pragma unroll
            for (int mf = 0; mf < 2; mf++)
#pragma unroll
                for (int nf = 0; nf < 4; nf++)
                    mma_f16(acc[mf][nf], ah[mf], &blv[nf >> 1][(nf & 1) * 2]);
#pragma unroll
            for (int mf = 0; mf < 2; mf++)
#pragma unroll
                for (int nf = 0; nf < 4; nf++)
                    mma_f16(acc[mf][nf], ah[mf], &bhv[nf >> 1][(nf & 1) * 2]);
        }
        __syncthreads();
        if (++sbuf == NSTAGE) sbuf = 0;
    }

    // ---- epilogue: bias + tanh + store (hi/lo halves or fp32) ----
    const int lr = lane >> 2;
    const int lc = lane & 3;
    float2 bv[4];
#pragma unroll
    for (int nf = 0; nf < 4; nf++) {
        const int cc = n0 + wn + nf * 8 + 2 * lc;
        bv[nf].x = bp[cc];
        bv[nf].y = bp[cc + 1];
    }

#pragma unroll
    for (int mf = 0; mf < 2; mf++) {
#pragma unroll
        for (int half = 0; half < 2; half++) {
            const int gm = m0 + wm + mf * 16 + lr + half * 8;
            if (gm >= Mv) continue;
            int crow;
            if      (MODE == 0) crow = g_pos[gm];
            else if (MODE == 1) crow = (abase - m0) + gm;
            else                crow = g_rows[gm];
            const size_t cb = (size_t)crow * N + n0 + wn + 2 * lc;
#pragma unroll
            for (int nf = 0; nf < 4; nf++) {
                float vx = tanhf(acc[mf][nf][half * 2 + 0] + bv[nf].x);
                float vy = tanhf(acc[mf][nf][half * 2 + 1] + bv[nf].y);
                if (MODE == 2) {
                    *(float2*)(Cf + cb + nf * 8) = make_float2(vx, vy);
                } else {
                    __half2 h = __floats2half2_rn(vx, vy);
                    float2 hf = __half22float2(h);
                    __half2 l = __floats2half2_rn(vx - hf.x, vy - hf.y);
                    *(__half2*)(Ch + cb + nf * 8) = h;
                    *(__half2*)(Cl + cb + nf * 8) = l;
                }
            }
        }
    }
}

// ---------------------------------------------------------------------------
extern "C" void kernel_launch(void* const* d_in, const int* in_sizes, int n_in,
                              void* d_out, int out_size)
{
    const float* obs    = (const float*)d_in[0];
    const int*   sw     = (const int*)  d_in[1];
    const float* pre_w  = (const float*)d_in[2];
    const float* pre_b  = (const float*)d_in[3];
    const float* exp_w  = (const float*)d_in[4];
    const float* exp_b  = (const float*)d_in[5];
    const float* post_w = (const float*)d_in[6];
    const float* post_b = (const float*)d_in[7];
    float*       out    = (float*)d_out;

    __half *obs_h, *obs_l, *prew_h, *prew_l, *expw_h, *expw_l, *postw_h, *postw_l;
    __half *x1_h, *x1_l, *x2_h, *x2_l;
    cudaGetSymbolAddress((void**)&obs_h,  g_obs_h);
    cudaGetSymbolAddress((void**)&obs_l,  g_obs_l);
    cudaGetSymbolAddress((void**)&prew_h, g_prew_h);
    cudaGetSymbolAddress((void**)&prew_l, g_prew_l);
    cudaGetSymbolAddress((void**)&expw_h, g_expw_h);
    cudaGetSymbolAddress((void**)&expw_l, g_expw_l);
    cudaGetSymbolAddress((void**)&postw_h, g_postw_h);
    cudaGetSymbolAddress((void**)&postw_l, g_postw_l);
    cudaGetSymbolAddress((void**)&x1_h, g_x1_h);
    cudaGetSymbolAddress((void**)&x1_l, g_x1_l);
    cudaGetSymbolAddress((void**)&x2_h, g_x2_h);
    cudaGetSymbolAddress((void**)&x2_l, g_x2_l);

    cudaFuncSetAttribute((const void*)gemm_mma<0>,
                         cudaFuncAttributeMaxDynamicSharedMemorySize, DYNSMEM);
    cudaFuncSetAttribute((const void*)gemm_mma<1>,
                         cudaFuncAttributeMaxDynamicSharedMemorySize, DYNSMEM);
    cudaFuncSetAttribute((const void*)gemm_mma<2>,
                         cudaFuncAttributeMaxDynamicSharedMemorySize, DYNSMEM);

    group_kernel<<<1, 256>>>(sw);

    // Pre-split inputs to fp16 hi/lo
    split_kernel<<<(BATCH * DIN / 4 + 255) / 256, 256>>>(obs,    obs_h,  obs_l,  BATCH * DIN / 4);
    split_kernel<<<(DH * DIN / 4 + 255) / 256, 256>>>(pre_w,  prew_h, prew_l, DH * DIN / 4);
    split_kernel<<<(NEXP * DH * DH / 4 + 255) / 256, 256>>>(exp_w, expw_h, expw_l, NEXP * DH * DH / 4);
    split_kernel<<<(DOUT * DH / 4 + 255) / 256, 256>>>(post_w, postw_h, postw_l, DOUT * DH / 4);

    // Stage 1: x1[g_pos[b]] = tanh(obs[b] @ pre_w^T + pre_b)  (writes hi/lo)
    gemm_mma<0><<<dim3(BATCH / BM, DH / BN), NTHREADS, DYNSMEM>>>(
        obs_h, obs_l, prew_h, prew_l, pre_b, x1_h, x1_l, nullptr, DH, DIN);

    // Stage 2: grouped expert GEMM (writes hi/lo)
    gemm_mma<1><<<dim3(BATCH / BM, DH / BN, NEXP), NTHREADS, DYNSMEM>>>(
        x1_h, x1_l, expw_h, expw_l, exp_b, x2_h, x2_l, nullptr, DH, DH);

    // Stage 3: out[g_rows[p]] = tanh(x2[p] @ post_w^T + post_b)  (fp32 out)
    gemm_mma<2><<<dim3(BATCH / BM, DOUT / BN), NTHREADS, DYNSMEM>>>(
        x2_h, x2_l, postw_h, postw_l, post_b, nullptr, nullptr, out, DOUT, DH);
}